// round 4
// baseline (speedup 1.0000x reference)
#include <cuda_runtime.h>
#include <math.h>

#define NN 100000
#define EE 1600000
#define HH 128
#define GG 256
#define LL 3
#define NB_SCAN ((NN + 1023) / 1024)   // 98

// ---------------- scratch (device globals; no allocation) ----------------
__device__ __align__(16) float g_h[NN * HH];
__device__ __align__(16) float g_t[NN * HH];
__device__ __align__(16) float g_r[NN * HH];
__device__ __align__(16) float g_tmp[NN * HH];
__device__ __align__(16) float g_out[GG * 16];
__device__ int    g_deg[NN];
__device__ int    g_incl[NN];
__device__ int    g_rowptr[NN + 1];
__device__ int    g_cursor[NN];
__device__ int    g_srcs[EE];
__device__ float4 g_ppf[EE];
__device__ int    g_bsum[128];
__device__ int    g_is64;
__device__ int    g_nz;

__device__ __forceinline__ float* getbuf(int id) {
    switch (id) {
        case 0: return g_h;
        case 1: return g_t;
        case 2: return g_r;
        default: return g_tmp;
    }
}

// index loader robust to int32 vs int64 storage
__device__ __forceinline__ int load_idx(const void* p, long long i, int is64) {
    if (is64) return (int)((const long long*)p)[i];
    return ((const int*)p)[i];
}

// ---------------- dtype detection: int64 high words are all zero ----------------
__global__ void k_detect(const void* ei) {
    __shared__ int s_nz;
    if (threadIdx.x == 0) s_nz = 0;
    __syncthreads();
    const int* w = (const int*)ei;
    int v = w[2 * threadIdx.x + 1];   // odd 32-bit words of the first 2048 "int64" slots
    int v2 = w[2 * (threadIdx.x + 1024) + 1];
    if ((v | v2) != 0) atomicOr(&s_nz, 1);
    __syncthreads();
    if (threadIdx.x == 0) g_is64 = s_nz ? 0 : 1;
}

// ---------------- init: zero deg + per-graph accumulator ----------------
__global__ void k_init() {
    int i = blockIdx.x * blockDim.x + threadIdx.x;
    if (i < GG * 16) g_out[i] = 0.f;
    if (i < NN) g_deg[i] = 0;
}

// ---------------- degree histogram over dst ----------------
__global__ void k_hist(const void* ei) {
    int e = blockIdx.x * blockDim.x + threadIdx.x;
    if (e < EE) {
        int d = load_idx(ei, (long long)EE + e, g_is64);
        atomicAdd(&g_deg[d], 1);
    }
}

// ---------------- scan (3 kernels) ----------------
__global__ void k_scan1() {
    __shared__ int s[1024];
    int tid = threadIdx.x;
    int i = blockIdx.x * 1024 + tid;
    int v = (i < NN) ? g_deg[i] : 0;
    s[tid] = v;
    __syncthreads();
    for (int off = 1; off < 1024; off <<= 1) {
        int a = (tid >= off) ? s[tid - off] : 0;
        __syncthreads();
        s[tid] += a;
        __syncthreads();
    }
    if (i < NN) g_incl[i] = s[tid];
    if (tid == 1023) g_bsum[blockIdx.x] = s[1023];
}

__global__ void k_scan2() {
    __shared__ int s[128];
    int tid = threadIdx.x;
    s[tid] = (tid < NB_SCAN) ? g_bsum[tid] : 0;
    __syncthreads();
    for (int off = 1; off < 128; off <<= 1) {
        int a = (tid >= off) ? s[tid - off] : 0;
        __syncthreads();
        s[tid] += a;
        __syncthreads();
    }
    if (tid < NB_SCAN) g_bsum[tid] = s[tid];
}

__global__ void k_fin() {
    int tid = threadIdx.x;
    int i = blockIdx.x * 1024 + tid;
    if (i < NN) {
        int off = blockIdx.x ? g_bsum[blockIdx.x - 1] : 0;
        int excl = g_incl[i] - g_deg[i] + off;
        g_rowptr[i] = excl;
        g_cursor[i] = excl;
    }
    if (i == 0) g_rowptr[NN] = EE;
}

// ---------------- per-edge PPF + CSR scatter ----------------
__device__ __forceinline__ float dot3(float ax, float ay, float az, float bx, float by, float bz) {
    return ax * bx + ay * by + az * bz;
}
__device__ __forceinline__ float crossnorm(float ax, float ay, float az, float bx, float by, float bz) {
    float cx = ay * bz - az * by;
    float cy = az * bx - ax * bz;
    float cz = ax * by - ay * bx;
    return sqrtf(cx * cx + cy * cy + cz * cz);
}

__global__ void k_scatter(const void* ei, const float* pos) {
    int e = blockIdx.x * blockDim.x + threadIdx.x;
    if (e >= EE) return;
    int is64 = g_is64;
    int s = load_idx(ei, e, is64);                   // src j
    int d = load_idx(ei, (long long)EE + e, is64);   // dst i
    float pix = pos[3 * d], piy = pos[3 * d + 1], piz = pos[3 * d + 2];
    float pjx = pos[3 * s], pjy = pos[3 * s + 1], pjz = pos[3 * s + 2];
    float nin = sqrtf(pix * pix + piy * piy + piz * piz) + 1e-12f;
    float njn = sqrtf(pjx * pjx + pjy * pjy + pjz * pjz) + 1e-12f;
    float nix = pix / nin, niy = piy / nin, niz = piz / nin;
    float njx = pjx / njn, njy = pjy / njn, njz = pjz / njn;
    float dx = pjx - pix, dy = pjy - piy, dz = pjz - piz;
    float f0 = sqrtf(dx * dx + dy * dy + dz * dz);
    float f1 = atan2f(crossnorm(nix, niy, niz, dx, dy, dz), dot3(nix, niy, niz, dx, dy, dz));
    float f2 = atan2f(crossnorm(njx, njy, njz, dx, dy, dz), dot3(njx, njy, njz, dx, dy, dz));
    float f3 = atan2f(crossnorm(nix, niy, niz, njx, njy, njz), dot3(nix, niy, niz, njx, njy, njz));
    int slot = atomicAdd(&g_cursor[d], 1);
    g_srcs[slot] = s;
    g_ppf[slot] = make_float4(f0, f1, f2, f3);
}

// ---------------- generic fused GEMM: Y = act(X @ W + bias[*deg]) ----------------
// BMODE: 0 = no bias, 1 = bias, 2 = bias * deg[row]
template <int K, int M, int BMODE, bool RELU>
__global__ void k_gemm(int xid, const float* Xext,
                       const float* W, const float* bias,
                       int yid, int nrows) {
    constexpr int NT = 64;
    constexpr int CG = M / 4;          // float4 columns
    constexpr int NG = 256 / CG;       // row groups
    constexpr int NPT = NT / NG;       // rows per thread
    constexpr int KC = 16;             // K-chunk
    __shared__ float Ws[KC * M];       // <= 8KB
    __shared__ float Xs[NT * K];       // <= 32KB

    const float* X = (xid >= 0) ? getbuf(xid) : Xext;
    float* Y = getbuf(yid);

    int tid = threadIdx.x;
    const int c = tid % CG;
    const int g = tid / CG;
    const float4* Ws4 = (const float4*)Ws;
    int ntiles = (nrows + NT - 1) / NT;

    for (int tile = blockIdx.x; tile < ntiles; tile += gridDim.x) {
        int row0 = tile * NT;
        __syncthreads();   // previous tile's readers done
        for (int i = tid; i < NT * K; i += 256) {
            int rr = i / K, kk = i % K;
            int r = row0 + rr;
            Xs[i] = (r < nrows) ? X[(long long)r * K + kk] : 0.f;
        }
        float4 acc[NPT];
#pragma unroll
        for (int r = 0; r < NPT; r++) acc[r] = make_float4(0.f, 0.f, 0.f, 0.f);

        for (int kc0 = 0; kc0 < K; kc0 += KC) {
            __syncthreads();
            for (int i = tid; i < KC * M; i += 256) Ws[i] = W[kc0 * M + i];
            __syncthreads();
#pragma unroll
            for (int k = 0; k < KC; k++) {
                float4 w = Ws4[k * CG + c];
#pragma unroll
                for (int r = 0; r < NPT; r++) {
                    float xv = Xs[(g * NPT + r) * K + kc0 + k];
                    acc[r].x = fmaf(xv, w.x, acc[r].x);
                    acc[r].y = fmaf(xv, w.y, acc[r].y);
                    acc[r].z = fmaf(xv, w.z, acc[r].z);
                    acc[r].w = fmaf(xv, w.w, acc[r].w);
                }
            }
        }
        float4 bv = make_float4(0.f, 0.f, 0.f, 0.f);
        if (BMODE >= 1) bv = ((const float4*)bias)[c];
#pragma unroll
        for (int r = 0; r < NPT; r++) {
            int row = row0 + g * NPT + r;
            if (row < nrows) {
                float sc = 1.f;
                if (BMODE == 2) sc = (float)g_deg[row];
                float4 v;
                v.x = acc[r].x + bv.x * sc;
                v.y = acc[r].y + bv.y * sc;
                v.z = acc[r].z + bv.z * sc;
                v.w = acc[r].w + bv.w * sc;
                if (RELU) {
                    v.x = fmaxf(v.x, 0.f);
                    v.y = fmaxf(v.y, 0.f);
                    v.z = fmaxf(v.z, 0.f);
                    v.w = fmaxf(v.w, 0.f);
                }
                ((float4*)Y)[(long long)row * CG + c] = v;
            }
        }
    }
}

// ---------------- edge gather: g_r[i] = sum_e relu(g_t[src_e] + ppf_e @ W1p + b1) ----------------
__global__ void k_gather(const float* W1p, const float* b1) {
    int lane = threadIdx.x & 31;
    int wid = (blockIdx.x * blockDim.x + threadIdx.x) >> 5;
    int nwarps = (gridDim.x * blockDim.x) >> 5;
    const float4* W4 = (const float4*)W1p;  // [4][32] float4
    float4 w0 = W4[0 * 32 + lane];
    float4 w1 = W4[1 * 32 + lane];
    float4 w2 = W4[2 * 32 + lane];
    float4 w3 = W4[3 * 32 + lane];
    float4 bb = ((const float4*)b1)[lane];
    const float4* t4 = (const float4*)g_t;
    float4* r4 = (float4*)g_r;
    for (int node = wid; node < NN; node += nwarps) {
        int s0 = g_rowptr[node];
        int s1 = g_rowptr[node + 1];
        float4 acc = make_float4(0.f, 0.f, 0.f, 0.f);
        for (int s = s0; s < s1; s++) {
            int src = g_srcs[s];
            float4 pf = g_ppf[s];
            float4 tv = t4[(long long)src * 32 + lane];
            float4 h;
            h.x = bb.x + tv.x;
            h.y = bb.y + tv.y;
            h.z = bb.z + tv.z;
            h.w = bb.w + tv.w;
            h.x = fmaf(pf.x, w0.x, h.x); h.y = fmaf(pf.x, w0.y, h.y); h.z = fmaf(pf.x, w0.z, h.z); h.w = fmaf(pf.x, w0.w, h.w);
            h.x = fmaf(pf.y, w1.x, h.x); h.y = fmaf(pf.y, w1.y, h.y); h.z = fmaf(pf.y, w1.z, h.z); h.w = fmaf(pf.y, w1.w, h.w);
            h.x = fmaf(pf.z, w2.x, h.x); h.y = fmaf(pf.z, w2.y, h.y); h.z = fmaf(pf.z, w2.z, h.z); h.w = fmaf(pf.z, w2.w, h.w);
            h.x = fmaf(pf.w, w3.x, h.x); h.y = fmaf(pf.w, w3.y, h.y); h.z = fmaf(pf.w, w3.z, h.z); h.w = fmaf(pf.w, w3.w, h.w);
            acc.x += fmaxf(h.x, 0.f);
            acc.y += fmaxf(h.y, 0.f);
            acc.z += fmaxf(h.z, 0.f);
            acc.w += fmaxf(h.w, 0.f);
        }
        r4[(long long)node * 32 + lane] = acc;
    }
}

// ---------------- per-graph reduction into device-static accumulator ----------------
__global__ void k_out(const void* batch) {
    int i = blockIdx.x * blockDim.x + threadIdx.x;
    if (i < NN * 16) {
        int n = i >> 4, j = i & 15;
        int b = load_idx(batch, n, g_is64);
        atomicAdd(&g_out[b * 16 + j], g_t[i]);
    }
}

// ---------------- plain-store copy into d_out ----------------
__global__ void k_copy(float* out) {
    int i = blockIdx.x * blockDim.x + threadIdx.x;
    if (i < GG * 16) out[i] = g_out[i];
}

// ---------------- launch ----------------
extern "C" void kernel_launch(void* const* d_in, const int* in_sizes, int n_in,
                              void* d_out, int out_size) {
    const float* x     = (const float*)d_in[0];
    const float* pos   = (const float*)d_in[1];
    const void*  ei    = d_in[2];
    const void*  batch = d_in[3];
    const float* nW1 = (const float*)d_in[4];
    const float* nb1 = (const float*)d_in[5];
    const float* nW2 = (const float*)d_in[6];
    const float* nb2 = (const float*)d_in[7];
    const float* lW1 = (const float*)d_in[8];
    const float* lb1 = (const float*)d_in[9];
    const float* lW2 = (const float*)d_in[10];
    const float* lb2 = (const float*)d_in[11];
    const float* gW1 = (const float*)d_in[12];
    const float* gb1 = (const float*)d_in[13];
    const float* gW2 = (const float*)d_in[14];
    const float* gb2 = (const float*)d_in[15];
    const float* l1W = (const float*)d_in[16];
    const float* l1b = (const float*)d_in[17];
    const float* l2W = (const float*)d_in[18];
    const float* l2b = (const float*)d_in[19];
    float* out = (float*)d_out;

    const int GB = 296;  // grid for GEMMs (~2 blocks/SM)

    k_detect<<<1, 1024>>>(ei);
    k_init<<<(NN + 255) / 256, 256>>>();
    k_hist<<<(EE + 255) / 256, 256>>>(ei);
    k_scan1<<<NB_SCAN, 1024>>>();
    k_scan2<<<1, 128>>>();
    k_fin<<<NB_SCAN, 1024>>>();
    k_scatter<<<(EE + 255) / 256, 256>>>(ei, pos);

    // node MLP: h = relu(x@nW1+nb1) @ nW2 + nb2    (buffers: 0=h,1=t,2=r,3=tmp)
    k_gemm<16, 128, 1, true><<<GB, 256>>>(-1, x, nW1, nb1, 3, NN);
    k_gemm<128, 128, 1, false><<<GB, 256>>>(3, nullptr, nW2, nb2, 0, NN);

    for (int l = 0; l < LL; l++) {
        const float* W1  = lW1 + l * 132 * 128;   // rows 0..127: h part
        const float* W1p = W1 + 128 * 128;        // rows 128..131: ppf part
        // t = h @ W1_h
        k_gemm<128, 128, 0, false><<<GB, 256>>>(0, nullptr, W1, nullptr, 1, NN);
        // r[i] = sum_edges relu(t[src] + ppf@W1p + b1)
        k_gather<<<1184, 256>>>(W1p, lb1 + l * 128);
        // agg = r @ W2 + deg*b2
        k_gemm<128, 128, 2, false><<<GB, 256>>>(2, nullptr, lW2 + l * 128 * 128, lb2 + l * 128, 3, NN);
        // v = relu(agg @ gW1 + gb1)
        k_gemm<128, 128, 1, true><<<GB, 256>>>(3, nullptr, gW1 + l * 128 * 128, gb1 + l * 128, 1, NN);
        // h = relu(v @ gW2 + gb2)
        k_gemm<128, 128, 1, true><<<GB, 256>>>(1, nullptr, gW2 + l * 128 * 128, gb2 + l * 128, 0, NN);
    }

    // head: tmp = relu(h@l1W+l1b); t = tmp@l2W+l2b; g_out = segment_sum(t, batch)
    k_gemm<128, 64, 1, true><<<GB, 256>>>(0, nullptr, l1W, l1b, 3, NN);
    k_gemm<64, 16, 1, false><<<GB, 256>>>(3, nullptr, l2W, l2b, 1, NN);
    k_out<<<(NN * 16 + 255) / 256, 256>>>(batch);
    k_copy<<<(GG * 16 + 255) / 256, 256>>>(out);
}

// round 5
// speedup vs baseline: 1.2665x; 1.2665x over previous
#include <cuda_runtime.h>
#include <math.h>

#define NN 100000
#define EE 1600000
#define HH 128
#define GG 256
#define LL 3
#define NB_SCAN ((NN + 1023) / 1024)   // 98

// ---------------- scratch (device globals; no allocation) ----------------
__device__ __align__(16) float g_h[NN * HH];
__device__ __align__(16) float g_t[NN * HH];
__device__ __align__(16) float g_r[NN * HH];
__device__ __align__(16) float g_tmp[NN * HH];
__device__ __align__(16) float g_out[GG * 16];
__device__ __align__(16) float g_F[HH * HH];   // fused weight product
__device__ __align__(16) float g_c[HH];        // fused bias vector
__device__ int    g_deg[NN];
__device__ int    g_incl[NN];
__device__ int    g_rowptr[NN + 1];
__device__ int    g_cursor[NN];
__device__ int    g_srcs[EE];
__device__ float4 g_ppf[EE];
__device__ int    g_bsum[128];
__device__ int    g_is64;

__device__ __forceinline__ float* getbuf(int id) {
    switch (id) {
        case 0: return g_h;
        case 1: return g_t;
        case 2: return g_r;
        default: return g_tmp;
    }
}

__device__ __forceinline__ int load_idx(const void* p, long long i, int is64) {
    if (is64) return (int)((const long long*)p)[i];
    return ((const int*)p)[i];
}

// ---------------- dtype detection: int64 high words are all zero ----------------
__global__ void k_detect(const void* ei) {
    __shared__ int s_nz;
    if (threadIdx.x == 0) s_nz = 0;
    __syncthreads();
    const int* w = (const int*)ei;
    int v = w[2 * threadIdx.x + 1];
    int v2 = w[2 * (threadIdx.x + 1024) + 1];
    if ((v | v2) != 0) atomicOr(&s_nz, 1);
    __syncthreads();
    if (threadIdx.x == 0) g_is64 = s_nz ? 0 : 1;
}

// ---------------- init ----------------
__global__ void k_init() {
    int i = blockIdx.x * blockDim.x + threadIdx.x;
    if (i < GG * 16) g_out[i] = 0.f;
    if (i < NN) g_deg[i] = 0;
}

// ---------------- degree histogram over dst ----------------
__global__ void k_hist(const void* ei) {
    int e = blockIdx.x * blockDim.x + threadIdx.x;
    if (e < EE) {
        int d = load_idx(ei, (long long)EE + e, g_is64);
        atomicAdd(&g_deg[d], 1);
    }
}

// ---------------- scan ----------------
__global__ void k_scan1() {
    __shared__ int s[1024];
    int tid = threadIdx.x;
    int i = blockIdx.x * 1024 + tid;
    int v = (i < NN) ? g_deg[i] : 0;
    s[tid] = v;
    __syncthreads();
    for (int off = 1; off < 1024; off <<= 1) {
        int a = (tid >= off) ? s[tid - off] : 0;
        __syncthreads();
        s[tid] += a;
        __syncthreads();
    }
    if (i < NN) g_incl[i] = s[tid];
    if (tid == 1023) g_bsum[blockIdx.x] = s[1023];
}

__global__ void k_scan2() {
    __shared__ int s[128];
    int tid = threadIdx.x;
    s[tid] = (tid < NB_SCAN) ? g_bsum[tid] : 0;
    __syncthreads();
    for (int off = 1; off < 128; off <<= 1) {
        int a = (tid >= off) ? s[tid - off] : 0;
        __syncthreads();
        s[tid] += a;
        __syncthreads();
    }
    if (tid < NB_SCAN) g_bsum[tid] = s[tid];
}

__global__ void k_fin() {
    int tid = threadIdx.x;
    int i = blockIdx.x * 1024 + tid;
    if (i < NN) {
        int off = blockIdx.x ? g_bsum[blockIdx.x - 1] : 0;
        int excl = g_incl[i] - g_deg[i] + off;
        g_rowptr[i] = excl;
        g_cursor[i] = excl;
    }
    if (i == 0) g_rowptr[NN] = EE;
}

// ---------------- per-edge PPF + CSR scatter ----------------
__device__ __forceinline__ float dot3(float ax, float ay, float az, float bx, float by, float bz) {
    return ax * bx + ay * by + az * bz;
}
__device__ __forceinline__ float crossnorm(float ax, float ay, float az, float bx, float by, float bz) {
    float cx = ay * bz - az * by;
    float cy = az * bx - ax * bz;
    float cz = ax * by - ay * bx;
    return sqrtf(cx * cx + cy * cy + cz * cz);
}

__global__ void k_scatter(const void* ei, const float* pos) {
    int e = blockIdx.x * blockDim.x + threadIdx.x;
    if (e >= EE) return;
    int is64 = g_is64;
    int s = load_idx(ei, e, is64);
    int d = load_idx(ei, (long long)EE + e, is64);
    float pix = pos[3 * d], piy = pos[3 * d + 1], piz = pos[3 * d + 2];
    float pjx = pos[3 * s], pjy = pos[3 * s + 1], pjz = pos[3 * s + 2];
    float nin = sqrtf(pix * pix + piy * piy + piz * piz) + 1e-12f;
    float njn = sqrtf(pjx * pjx + pjy * pjy + pjz * pjz) + 1e-12f;
    float nix = pix / nin, niy = piy / nin, niz = piz / nin;
    float njx = pjx / njn, njy = pjy / njn, njz = pjz / njn;
    float dx = pjx - pix, dy = pjy - piy, dz = pjz - piz;
    float f0 = sqrtf(dx * dx + dy * dy + dz * dz);
    float f1 = atan2f(crossnorm(nix, niy, niz, dx, dy, dz), dot3(nix, niy, niz, dx, dy, dz));
    float f2 = atan2f(crossnorm(njx, njy, njz, dx, dy, dz), dot3(njx, njy, njz, dx, dy, dz));
    float f3 = atan2f(crossnorm(nix, niy, niz, njx, njy, njz), dot3(nix, niy, niz, njx, njy, njz));
    int slot = atomicAdd(&g_cursor[d], 1);
    g_srcs[slot] = s;
    g_ppf[slot] = make_float4(f0, f1, f2, f3);
}

// ---------------- small precompute: g_F = A@B (128x128), g_c = v@B ----------------
__global__ void k_combine(const float* A, const float* B, const float* v) {
    int col = threadIdx.x;
    int row = blockIdx.x;
    if (row < 128) {
        float s = 0.f;
        for (int k = 0; k < 128; k++) s = fmaf(A[row * 128 + k], B[k * 128 + col], s);
        g_F[row * 128 + col] = s;
    } else {
        float s = 0.f;
        for (int k = 0; k < 128; k++) s = fmaf(v[k], B[k * 128 + col], s);
        g_c[col] = s;
    }
}

// ---------------- big GEMM: Y = act(X @ W [+ bias] [+ deg*bias2]), K=M=128 ----------------
// 256 threads, 128x128 tile, 8x8 per thread.
// BMODE: 0 none, 1 bias (bias==nullptr -> use g_c), 3 bias + deg*g_c
template <int BMODE, bool RELU>
__global__ void k_gemm128(int xid, const float* Xext, const float* Wext, int wsrc,
                          const float* bias, int yid, int nrows) {
    __shared__ float Xs[16 * 128];   // [k][row]
    __shared__ float Ws[16 * 128];   // [k][col]
    const float* X = (xid >= 0) ? getbuf(xid) : Xext;
    const float* W = wsrc ? g_F : Wext;
    float* Y = getbuf(yid);

    int tid = threadIdx.x;
    int tx = tid & 15;        // col group
    int ty = tid >> 4;        // row group
    int ntiles = (nrows + 127) / 128;

    for (int tile = blockIdx.x; tile < ntiles; tile += gridDim.x) {
        int row0 = tile * 128;
        float acc[8][8];
#pragma unroll
        for (int r = 0; r < 8; r++)
#pragma unroll
            for (int cc = 0; cc < 8; cc++) acc[r][cc] = 0.f;

        for (int kc = 0; kc < 128; kc += 16) {
            __syncthreads();
#pragma unroll
            for (int i = tid; i < 512; i += 256) {
                int row = i >> 2, kq = (i & 3) * 4;
                float4 v = make_float4(0.f, 0.f, 0.f, 0.f);
                int rr = row0 + row;
                if (rr < nrows) v = *(const float4*)&X[(long long)rr * 128 + kc + kq];
                Xs[(kq + 0) * 128 + row] = v.x;
                Xs[(kq + 1) * 128 + row] = v.y;
                Xs[(kq + 2) * 128 + row] = v.z;
                Xs[(kq + 3) * 128 + row] = v.w;
            }
#pragma unroll
            for (int i = tid; i < 512; i += 256) {
                int k = i >> 5, cq = (i & 31) * 4;
                *(float4*)&Ws[k * 128 + cq] = *(const float4*)&W[(kc + k) * 128 + cq];
            }
            __syncthreads();
#pragma unroll
            for (int k = 0; k < 16; k++) {
                float a[8], b[8];
                *(float4*)&a[0] = *(float4*)&Xs[k * 128 + ty * 8];
                *(float4*)&a[4] = *(float4*)&Xs[k * 128 + ty * 8 + 4];
                *(float4*)&b[0] = *(float4*)&Ws[k * 128 + tx * 8];
                *(float4*)&b[4] = *(float4*)&Ws[k * 128 + tx * 8 + 4];
#pragma unroll
                for (int r = 0; r < 8; r++)
#pragma unroll
                    for (int cc = 0; cc < 8; cc++)
                        acc[r][cc] = fmaf(a[r], b[cc], acc[r][cc]);
            }
        }
        float bv[8], b2[8];
#pragma unroll
        for (int cc = 0; cc < 8; cc++) { bv[cc] = 0.f; b2[cc] = 0.f; }
        if (BMODE >= 1) {
            const float* bp = (bias != nullptr) ? bias : g_c;
            *(float4*)&bv[0] = *(const float4*)&bp[tx * 8];
            *(float4*)&bv[4] = *(const float4*)&bp[tx * 8 + 4];
        }
        if (BMODE == 3) {
            *(float4*)&b2[0] = *(const float4*)&g_c[tx * 8];
            *(float4*)&b2[4] = *(const float4*)&g_c[tx * 8 + 4];
        }
#pragma unroll
        for (int r = 0; r < 8; r++) {
            int row = row0 + ty * 8 + r;
            if (row < nrows) {
                float sc = (BMODE == 3) ? (float)g_deg[row] : 0.f;
                float o[8];
#pragma unroll
                for (int cc = 0; cc < 8; cc++) {
                    float v = acc[r][cc] + bv[cc] + sc * b2[cc];
                    o[cc] = RELU ? fmaxf(v, 0.f) : v;
                }
                *(float4*)&Y[(long long)row * 128 + tx * 8]     = *(float4*)&o[0];
                *(float4*)&Y[(long long)row * 128 + tx * 8 + 4] = *(float4*)&o[4];
            }
        }
    }
}

// ---------------- small GEMM (K=16 node in + heads) ----------------
template <int K, int M, int BMODE, bool RELU>
__global__ void k_gemm(int xid, const float* Xext,
                       const float* W, const float* bias,
                       int yid, int nrows) {
    constexpr int NT = 64;
    constexpr int CG = M / 4;
    constexpr int NG = 256 / CG;
    constexpr int NPT = NT / NG;
    constexpr int KC = 16;
    __shared__ float Ws[KC * M];
    __shared__ float Xs[NT * K];

    const float* X = (xid >= 0) ? getbuf(xid) : Xext;
    float* Y = getbuf(yid);

    int tid = threadIdx.x;
    const int c = tid % CG;
    const int g = tid / CG;
    const float4* Ws4 = (const float4*)Ws;
    int ntiles = (nrows + NT - 1) / NT;

    for (int tile = blockIdx.x; tile < ntiles; tile += gridDim.x) {
        int row0 = tile * NT;
        __syncthreads();
        for (int i = tid; i < NT * K; i += 256) {
            int rr = i / K, kk = i % K;
            int r = row0 + rr;
            Xs[i] = (r < nrows) ? X[(long long)r * K + kk] : 0.f;
        }
        float4 acc[NPT];
#pragma unroll
        for (int r = 0; r < NPT; r++) acc[r] = make_float4(0.f, 0.f, 0.f, 0.f);

        for (int kc0 = 0; kc0 < K; kc0 += KC) {
            __syncthreads();
            for (int i = tid; i < KC * M; i += 256) Ws[i] = W[kc0 * M + i];
            __syncthreads();
#pragma unroll
            for (int k = 0; k < KC; k++) {
                float4 w = Ws4[k * CG + c];
#pragma unroll
                for (int r = 0; r < NPT; r++) {
                    float xv = Xs[(g * NPT + r) * K + kc0 + k];
                    acc[r].x = fmaf(xv, w.x, acc[r].x);
                    acc[r].y = fmaf(xv, w.y, acc[r].y);
                    acc[r].z = fmaf(xv, w.z, acc[r].z);
                    acc[r].w = fmaf(xv, w.w, acc[r].w);
                }
            }
        }
        float4 bv = make_float4(0.f, 0.f, 0.f, 0.f);
        if (BMODE >= 1) bv = ((const float4*)bias)[c];
#pragma unroll
        for (int r = 0; r < NPT; r++) {
            int row = row0 + g * NPT + r;
            if (row < nrows) {
                float4 v;
                v.x = acc[r].x + bv.x;
                v.y = acc[r].y + bv.y;
                v.z = acc[r].z + bv.z;
                v.w = acc[r].w + bv.w;
                if (RELU) {
                    v.x = fmaxf(v.x, 0.f);
                    v.y = fmaxf(v.y, 0.f);
                    v.z = fmaxf(v.z, 0.f);
                    v.w = fmaxf(v.w, 0.f);
                }
                ((float4*)Y)[(long long)row * CG + c] = v;
            }
        }
    }
}

// ---------------- edge gather ----------------
__global__ void k_gather(const float* W1p, const float* b1) {
    int lane = threadIdx.x & 31;
    int wid = (blockIdx.x * blockDim.x + threadIdx.x) >> 5;
    int nwarps = (gridDim.x * blockDim.x) >> 5;
    const float4* W4 = (const float4*)W1p;
    float4 w0 = W4[0 * 32 + lane];
    float4 w1 = W4[1 * 32 + lane];
    float4 w2 = W4[2 * 32 + lane];
    float4 w3 = W4[3 * 32 + lane];
    float4 bb = ((const float4*)b1)[lane];
    const float4* t4 = (const float4*)g_t;
    float4* r4 = (float4*)g_r;
    for (int node = wid; node < NN; node += nwarps) {
        int s0 = g_rowptr[node];
        int s1 = g_rowptr[node + 1];
        float4 acc = make_float4(0.f, 0.f, 0.f, 0.f);
        for (int s = s0; s < s1; s++) {
            int src = g_srcs[s];
            float4 pf = g_ppf[s];
            float4 tv = t4[(long long)src * 32 + lane];
            float4 h;
            h.x = bb.x + tv.x;
            h.y = bb.y + tv.y;
            h.z = bb.z + tv.z;
            h.w = bb.w + tv.w;
            h.x = fmaf(pf.x, w0.x, h.x); h.y = fmaf(pf.x, w0.y, h.y); h.z = fmaf(pf.x, w0.z, h.z); h.w = fmaf(pf.x, w0.w, h.w);
            h.x = fmaf(pf.y, w1.x, h.x); h.y = fmaf(pf.y, w1.y, h.y); h.z = fmaf(pf.y, w1.z, h.z); h.w = fmaf(pf.y, w1.w, h.w);
            h.x = fmaf(pf.z, w2.x, h.x); h.y = fmaf(pf.z, w2.y, h.y); h.z = fmaf(pf.z, w2.z, h.z); h.w = fmaf(pf.z, w2.w, h.w);
            h.x = fmaf(pf.w, w3.x, h.x); h.y = fmaf(pf.w, w3.y, h.y); h.z = fmaf(pf.w, w3.z, h.z); h.w = fmaf(pf.w, w3.w, h.w);
            acc.x += fmaxf(h.x, 0.f);
            acc.y += fmaxf(h.y, 0.f);
            acc.z += fmaxf(h.z, 0.f);
            acc.w += fmaxf(h.w, 0.f);
        }
        r4[(long long)node * 32 + lane] = acc;
    }
}

// ---------------- per-graph reduction ----------------
__global__ void k_out(const void* batch) {
    int i = blockIdx.x * blockDim.x + threadIdx.x;
    if (i < NN * 16) {
        int n = i >> 4, j = i & 15;
        int b = load_idx(batch, n, g_is64);
        atomicAdd(&g_out[b * 16 + j], g_t[i]);
    }
}

__global__ void k_copy(float* out) {
    int i = blockIdx.x * blockDim.x + threadIdx.x;
    if (i < GG * 16) out[i] = g_out[i];
}

// ---------------- launch ----------------
extern "C" void kernel_launch(void* const* d_in, const int* in_sizes, int n_in,
                              void* d_out, int out_size) {
    const float* x     = (const float*)d_in[0];
    const float* pos   = (const float*)d_in[1];
    const void*  ei    = d_in[2];
    const void*  batch = d_in[3];
    const float* nW1 = (const float*)d_in[4];
    const float* nb1 = (const float*)d_in[5];
    const float* nW2 = (const float*)d_in[6];
    const float* nb2 = (const float*)d_in[7];
    const float* lW1 = (const float*)d_in[8];
    const float* lb1 = (const float*)d_in[9];
    const float* lW2 = (const float*)d_in[10];
    const float* lb2 = (const float*)d_in[11];
    const float* gW1 = (const float*)d_in[12];
    const float* gb1 = (const float*)d_in[13];
    const float* gW2 = (const float*)d_in[14];
    const float* gb2 = (const float*)d_in[15];
    const float* l1W = (const float*)d_in[16];
    const float* l1b = (const float*)d_in[17];
    const float* l2W = (const float*)d_in[18];
    const float* l2b = (const float*)d_in[19];
    float* out = (float*)d_out;

    const int GB = 296;

    k_detect<<<1, 1024>>>(ei);
    k_init<<<(NN + 255) / 256, 256>>>();
    k_hist<<<(EE + 255) / 256, 256>>>(ei);
    k_scan1<<<NB_SCAN, 1024>>>();
    k_scan2<<<1, 128>>>();
    k_fin<<<NB_SCAN, 1024>>>();
    k_scatter<<<(EE + 255) / 256, 256>>>(ei, pos);

    // q = relu(x@nW1 + nb1)                          -> buf3
    k_gemm<16, 128, 1, true><<<GB, 256>>>(-1, x, nW1, nb1, 3, NN);
    // g_F = nW2@W1h_0, g_c = nb2@W1h_0 ; t0 = q@g_F + g_c -> buf1
    k_combine<<<129, 128>>>(nW2, lW1 + 0 * 132 * 128, nb2);
    k_gemm128<1, false><<<GB, 256>>>(3, nullptr, nullptr, 1, nullptr, 1, NN);

    for (int l = 0; l < LL; l++) {
        const float* W1p = lW1 + l * 132 * 128 + 128 * 128;  // ppf rows of local W1
        // r[i] = sum_edges relu(t[src] + ppf@W1p + b1)   (buf1 -> buf2)
        k_gather<<<1184, 256>>>(W1p, lb1 + l * 128);
        // g_F = lW2_l@gW1_l, g_c = lb2_l@gW1_l
        k_combine<<<129, 128>>>(lW2 + l * 128 * 128, gW1 + l * 128 * 128, lb2 + l * 128);
        // u = relu(r@g_F + gb1 + deg*g_c)                -> buf3
        k_gemm128<3, true><<<GB, 256>>>(2, nullptr, nullptr, 1, gb1 + l * 128, 3, NN);
        // h = relu(u@gW2 + gb2)                          -> buf0
        k_gemm128<1, true><<<GB, 256>>>(3, nullptr, gW2 + l * 128 * 128, 0, gb2 + l * 128, 0, NN);
        if (l + 1 < LL) {
            // t_{l+1} = h @ W1h_{l+1}                    -> buf1
            k_gemm128<0, false><<<GB, 256>>>(0, nullptr, lW1 + (l + 1) * 132 * 128, 0, nullptr, 1, NN);
        }
    }

    // head: buf0 -> buf3 -> buf1 -> out
    k_gemm<128, 64, 1, true><<<GB, 256>>>(0, nullptr, l1W, l1b, 3, NN);
    k_gemm<64, 16, 1, false><<<GB, 256>>>(3, nullptr, l2W, l2b, 1, NN);
    k_out<<<(NN * 16 + 255) / 256, 256>>>(batch);
    k_copy<<<(GG * 16 + 255) / 256, 256>>>(out);
}

// round 6
// speedup vs baseline: 1.2907x; 1.0191x over previous
#include <cuda_runtime.h>
#include <math.h>

#define NN 100000
#define EE 1600000
#define HH 128
#define GG 256
#define LL 3
#define NB_SCAN ((NN + 1023) / 1024)   // 98

// packed f32x2 helpers (Blackwell double-rate fp32)
#define PACK2(d, lo, hi) asm("mov.b64 %0, {%1, %2};" : "=l"(d) : "f"(lo), "f"(hi))
#define FMA2(acc, a, b)  asm("fma.rn.f32x2 %0, %1, %2, %0;" : "+l"(acc) : "l"(a), "l"(b))
#define UNPACK2(lo, hi, s) asm("mov.b64 {%0, %1}, %2;" : "=f"(lo), "=f"(hi) : "l"(s))

// ---------------- scratch (device globals; no allocation) ----------------
__device__ __align__(16) float g_h[NN * HH];
__device__ __align__(16) float g_t[NN * HH];
__device__ __align__(16) float g_r[NN * HH];
__device__ __align__(16) float g_tmp[NN * HH];
__device__ __align__(16) float g_out[GG * 16];
__device__ __align__(16) float g_F[HH * HH];   // fused weight product
__device__ __align__(16) float g_c[HH];        // fused bias vector
__device__ int    g_deg[NN];
__device__ int    g_incl[NN];
__device__ int    g_rowptr[NN + 1];
__device__ int    g_cursor[NN];
__device__ int    g_srcs[EE];
__device__ float4 g_ppf[EE];
__device__ int    g_bsum[128];
__device__ int    g_is64;

__device__ __forceinline__ float* getbuf(int id) {
    switch (id) {
        case 0: return g_h;
        case 1: return g_t;
        case 2: return g_r;
        default: return g_tmp;
    }
}

__device__ __forceinline__ int load_idx(const void* p, long long i, int is64) {
    if (is64) return (int)((const long long*)p)[i];
    return ((const int*)p)[i];
}

// ---------------- dtype detection: int64 high words are all zero ----------------
__global__ void k_detect(const void* ei) {
    __shared__ int s_nz;
    if (threadIdx.x == 0) s_nz = 0;
    __syncthreads();
    const int* w = (const int*)ei;
    int v = w[2 * threadIdx.x + 1];
    int v2 = w[2 * (threadIdx.x + 1024) + 1];
    if ((v | v2) != 0) atomicOr(&s_nz, 1);
    __syncthreads();
    if (threadIdx.x == 0) g_is64 = s_nz ? 0 : 1;
}

// ---------------- init ----------------
__global__ void k_init() {
    int i = blockIdx.x * blockDim.x + threadIdx.x;
    if (i < GG * 16) g_out[i] = 0.f;
    if (i < NN) g_deg[i] = 0;
}

// ---------------- degree histogram over dst ----------------
__global__ void k_hist(const void* ei) {
    int e = blockIdx.x * blockDim.x + threadIdx.x;
    if (e < EE) {
        int d = load_idx(ei, (long long)EE + e, g_is64);
        atomicAdd(&g_deg[d], 1);
    }
}

// ---------------- scan ----------------
__global__ void k_scan1() {
    __shared__ int s[1024];
    int tid = threadIdx.x;
    int i = blockIdx.x * 1024 + tid;
    int v = (i < NN) ? g_deg[i] : 0;
    s[tid] = v;
    __syncthreads();
    for (int off = 1; off < 1024; off <<= 1) {
        int a = (tid >= off) ? s[tid - off] : 0;
        __syncthreads();
        s[tid] += a;
        __syncthreads();
    }
    if (i < NN) g_incl[i] = s[tid];
    if (tid == 1023) g_bsum[blockIdx.x] = s[1023];
}

__global__ void k_scan2() {
    __shared__ int s[128];
    int tid = threadIdx.x;
    s[tid] = (tid < NB_SCAN) ? g_bsum[tid] : 0;
    __syncthreads();
    for (int off = 1; off < 128; off <<= 1) {
        int a = (tid >= off) ? s[tid - off] : 0;
        __syncthreads();
        s[tid] += a;
        __syncthreads();
    }
    if (tid < NB_SCAN) g_bsum[tid] = s[tid];
}

__global__ void k_fin() {
    int tid = threadIdx.x;
    int i = blockIdx.x * 1024 + tid;
    if (i < NN) {
        int off = blockIdx.x ? g_bsum[blockIdx.x - 1] : 0;
        int excl = g_incl[i] - g_deg[i] + off;
        g_rowptr[i] = excl;
        g_cursor[i] = excl;
    }
    if (i == 0) g_rowptr[NN] = EE;
}

// ---------------- per-edge PPF + CSR scatter ----------------
__device__ __forceinline__ float dot3(float ax, float ay, float az, float bx, float by, float bz) {
    return ax * bx + ay * by + az * bz;
}
__device__ __forceinline__ float crossnorm(float ax, float ay, float az, float bx, float by, float bz) {
    float cx = ay * bz - az * by;
    float cy = az * bx - ax * bz;
    float cz = ax * by - ay * bx;
    return sqrtf(cx * cx + cy * cy + cz * cz);
}

__global__ void k_scatter(const void* ei, const float* pos) {
    int e = blockIdx.x * blockDim.x + threadIdx.x;
    if (e >= EE) return;
    int is64 = g_is64;
    int s = load_idx(ei, e, is64);
    int d = load_idx(ei, (long long)EE + e, is64);
    float pix = pos[3 * d], piy = pos[3 * d + 1], piz = pos[3 * d + 2];
    float pjx = pos[3 * s], pjy = pos[3 * s + 1], pjz = pos[3 * s + 2];
    float nin = sqrtf(pix * pix + piy * piy + piz * piz) + 1e-12f;
    float njn = sqrtf(pjx * pjx + pjy * pjy + pjz * pjz) + 1e-12f;
    float nix = pix / nin, niy = piy / nin, niz = piz / nin;
    float njx = pjx / njn, njy = pjy / njn, njz = pjz / njn;
    float dx = pjx - pix, dy = pjy - piy, dz = pjz - piz;
    float f0 = sqrtf(dx * dx + dy * dy + dz * dz);
    float f1 = atan2f(crossnorm(nix, niy, niz, dx, dy, dz), dot3(nix, niy, niz, dx, dy, dz));
    float f2 = atan2f(crossnorm(njx, njy, njz, dx, dy, dz), dot3(njx, njy, njz, dx, dy, dz));
    float f3 = atan2f(crossnorm(nix, niy, niz, njx, njy, njz), dot3(nix, niy, niz, njx, njy, njz));
    int slot = atomicAdd(&g_cursor[d], 1);
    g_srcs[slot] = s;
    g_ppf[slot] = make_float4(f0, f1, f2, f3);
}

// ---------------- small precompute: g_F = A@B (128x128), g_c = v@B ----------------
__global__ void k_combine(const float* A, const float* B, const float* v) {
    int col = threadIdx.x;
    int row = blockIdx.x;
    if (row < 128) {
        float s = 0.f;
        for (int k = 0; k < 128; k++) s = fmaf(A[row * 128 + k], B[k * 128 + col], s);
        g_F[row * 128 + col] = s;
    } else {
        float s = 0.f;
        for (int k = 0; k < 128; k++) s = fmaf(v[k], B[k * 128 + col], s);
        g_c[col] = s;
    }
}

// ---------------- big GEMM (packed f32x2): Y = act(X @ W [+ bias] [+ deg*g_c]) ----------------
// 256 threads, 128x128 tile, 8x8 per thread, fma.rn.f32x2 inner loop.
// BMODE: 0 none, 1 bias (bias==nullptr -> use g_c), 3 bias + deg*g_c
template <int BMODE, bool RELU>
__global__ void k_gemm128(int xid, const float* Xext, const float* Wext, int wsrc,
                          const float* bias, int yid, int nrows) {
    __shared__ float Xs[16 * 128];   // [k][row]
    __shared__ float Ws[16 * 128];   // [k][col]
    const float* X = (xid >= 0) ? getbuf(xid) : Xext;
    const float* W = wsrc ? g_F : Wext;
    float* Y = getbuf(yid);

    int tid = threadIdx.x;
    int tx = tid & 15;        // col group
    int ty = tid >> 4;        // row group
    int ntiles = (nrows + 127) / 128;

    for (int tile = blockIdx.x; tile < ntiles; tile += gridDim.x) {
        int row0 = tile * 128;
        unsigned long long acc2[8][4];
#pragma unroll
        for (int r = 0; r < 8; r++)
#pragma unroll
            for (int j = 0; j < 4; j++) acc2[r][j] = 0ull;

        for (int kc = 0; kc < 128; kc += 16) {
            __syncthreads();
#pragma unroll
            for (int i = tid; i < 512; i += 256) {
                int row = i >> 2, kq = (i & 3) * 4;
                float4 v = make_float4(0.f, 0.f, 0.f, 0.f);
                int rr = row0 + row;
                if (rr < nrows) v = *(const float4*)&X[(long long)rr * 128 + kc + kq];
                Xs[(kq + 0) * 128 + row] = v.x;
                Xs[(kq + 1) * 128 + row] = v.y;
                Xs[(kq + 2) * 128 + row] = v.z;
                Xs[(kq + 3) * 128 + row] = v.w;
            }
#pragma unroll
            for (int i = tid; i < 512; i += 256) {
                int k = i >> 5, cq = (i & 31) * 4;
                *(float4*)&Ws[k * 128 + cq] = *(const float4*)&W[(kc + k) * 128 + cq];
            }
            __syncthreads();
#pragma unroll
            for (int k = 0; k < 16; k++) {
                float4 a0 = *(float4*)&Xs[k * 128 + ty * 8];
                float4 a1 = *(float4*)&Xs[k * 128 + ty * 8 + 4];
                float4 b0 = *(float4*)&Ws[k * 128 + tx * 8];
                float4 b1 = *(float4*)&Ws[k * 128 + tx * 8 + 4];
                unsigned long long bq[4];
                PACK2(bq[0], b0.x, b0.y);
                PACK2(bq[1], b0.z, b0.w);
                PACK2(bq[2], b1.x, b1.y);
                PACK2(bq[3], b1.z, b1.w);
                float ar[8] = {a0.x, a0.y, a0.z, a0.w, a1.x, a1.y, a1.z, a1.w};
#pragma unroll
                for (int r = 0; r < 8; r++) {
                    unsigned long long aa;
                    PACK2(aa, ar[r], ar[r]);
                    FMA2(acc2[r][0], aa, bq[0]);
                    FMA2(acc2[r][1], aa, bq[1]);
                    FMA2(acc2[r][2], aa, bq[2]);
                    FMA2(acc2[r][3], aa, bq[3]);
                }
            }
        }
        // epilogue
        float bv[8], b2[8];
#pragma unroll
        for (int cc = 0; cc < 8; cc++) { bv[cc] = 0.f; b2[cc] = 0.f; }
        if (BMODE >= 1) {
            const float* bp = (bias != nullptr) ? bias : g_c;
            *(float4*)&bv[0] = *(const float4*)&bp[tx * 8];
            *(float4*)&bv[4] = *(const float4*)&bp[tx * 8 + 4];
        }
        if (BMODE == 3) {
            *(float4*)&b2[0] = *(const float4*)&g_c[tx * 8];
            *(float4*)&b2[4] = *(const float4*)&g_c[tx * 8 + 4];
        }
#pragma unroll
        for (int r = 0; r < 8; r++) {
            int row = row0 + ty * 8 + r;
            if (row < nrows) {
                float sc = (BMODE == 3) ? (float)g_deg[row] : 0.f;
                float o[8];
#pragma unroll
                for (int j = 0; j < 4; j++) {
                    float lo, hi;
                    UNPACK2(lo, hi, acc2[r][j]);
                    float v0 = lo + bv[2 * j]     + sc * b2[2 * j];
                    float v1 = hi + bv[2 * j + 1] + sc * b2[2 * j + 1];
                    o[2 * j]     = RELU ? fmaxf(v0, 0.f) : v0;
                    o[2 * j + 1] = RELU ? fmaxf(v1, 0.f) : v1;
                }
                *(float4*)&Y[(long long)row * 128 + tx * 8]     = *(float4*)&o[0];
                *(float4*)&Y[(long long)row * 128 + tx * 8 + 4] = *(float4*)&o[4];
            }
        }
    }
}

// ---------------- small GEMM (K=16 node in + heads) ----------------
template <int K, int M, int BMODE, bool RELU>
__global__ void k_gemm(int xid, const float* Xext,
                       const float* W, const float* bias,
                       int yid, int nrows) {
    constexpr int NT = 64;
    constexpr int CG = M / 4;
    constexpr int NG = 256 / CG;
    constexpr int NPT = NT / NG;
    constexpr int KC = 16;
    __shared__ float Ws[KC * M];
    __shared__ float Xs[NT * K];

    const float* X = (xid >= 0) ? getbuf(xid) : Xext;
    float* Y = getbuf(yid);

    int tid = threadIdx.x;
    const int c = tid % CG;
    const int g = tid / CG;
    const float4* Ws4 = (const float4*)Ws;
    int ntiles = (nrows + NT - 1) / NT;

    for (int tile = blockIdx.x; tile < ntiles; tile += gridDim.x) {
        int row0 = tile * NT;
        __syncthreads();
        for (int i = tid; i < NT * K; i += 256) {
            int rr = i / K, kk = i % K;
            int r = row0 + rr;
            Xs[i] = (r < nrows) ? X[(long long)r * K + kk] : 0.f;
        }
        float4 acc[NPT];
#pragma unroll
        for (int r = 0; r < NPT; r++) acc[r] = make_float4(0.f, 0.f, 0.f, 0.f);

        for (int kc0 = 0; kc0 < K; kc0 += KC) {
            __syncthreads();
            for (int i = tid; i < KC * M; i += 256) Ws[i] = W[kc0 * M + i];
            __syncthreads();
#pragma unroll
            for (int k = 0; k < KC; k++) {
                float4 w = Ws4[k * CG + c];
#pragma unroll
                for (int r = 0; r < NPT; r++) {
                    float xv = Xs[(g * NPT + r) * K + kc0 + k];
                    acc[r].x = fmaf(xv, w.x, acc[r].x);
                    acc[r].y = fmaf(xv, w.y, acc[r].y);
                    acc[r].z = fmaf(xv, w.z, acc[r].z);
                    acc[r].w = fmaf(xv, w.w, acc[r].w);
                }
            }
        }
        float4 bv = make_float4(0.f, 0.f, 0.f, 0.f);
        if (BMODE >= 1) bv = ((const float4*)bias)[c];
#pragma unroll
        for (int r = 0; r < NPT; r++) {
            int row = row0 + g * NPT + r;
            if (row < nrows) {
                float4 v;
                v.x = acc[r].x + bv.x;
                v.y = acc[r].y + bv.y;
                v.z = acc[r].z + bv.z;
                v.w = acc[r].w + bv.w;
                if (RELU) {
                    v.x = fmaxf(v.x, 0.f);
                    v.y = fmaxf(v.y, 0.f);
                    v.z = fmaxf(v.z, 0.f);
                    v.w = fmaxf(v.w, 0.f);
                }
                ((float4*)Y)[(long long)row * CG + c] = v;
            }
        }
    }
}

// ---------------- edge gather ----------------
__global__ void k_gather(const float* W1p, const float* b1) {
    int lane = threadIdx.x & 31;
    int wid = (blockIdx.x * blockDim.x + threadIdx.x) >> 5;
    int nwarps = (gridDim.x * blockDim.x) >> 5;
    const float4* W4 = (const float4*)W1p;
    float4 w0 = W4[0 * 32 + lane];
    float4 w1 = W4[1 * 32 + lane];
    float4 w2 = W4[2 * 32 + lane];
    float4 w3 = W4[3 * 32 + lane];
    float4 bb = ((const float4*)b1)[lane];
    const float4* t4 = (const float4*)g_t;
    float4* r4 = (float4*)g_r;
    for (int node = wid; node < NN; node += nwarps) {
        int s0 = g_rowptr[node];
        int s1 = g_rowptr[node + 1];
        float4 acc = make_float4(0.f, 0.f, 0.f, 0.f);
        for (int s = s0; s < s1; s++) {
            int src = g_srcs[s];
            float4 pf = g_ppf[s];
            float4 tv = t4[(long long)src * 32 + lane];
            float4 h;
            h.x = bb.x + tv.x;
            h.y = bb.y + tv.y;
            h.z = bb.z + tv.z;
            h.w = bb.w + tv.w;
            h.x = fmaf(pf.x, w0.x, h.x); h.y = fmaf(pf.x, w0.y, h.y); h.z = fmaf(pf.x, w0.z, h.z); h.w = fmaf(pf.x, w0.w, h.w);
            h.x = fmaf(pf.y, w1.x, h.x); h.y = fmaf(pf.y, w1.y, h.y); h.z = fmaf(pf.y, w1.z, h.z); h.w = fmaf(pf.y, w1.w, h.w);
            h.x = fmaf(pf.z, w2.x, h.x); h.y = fmaf(pf.z, w2.y, h.y); h.z = fmaf(pf.z, w2.z, h.z); h.w = fmaf(pf.z, w2.w, h.w);
            h.x = fmaf(pf.w, w3.x, h.x); h.y = fmaf(pf.w, w3.y, h.y); h.z = fmaf(pf.w, w3.z, h.z); h.w = fmaf(pf.w, w3.w, h.w);
            acc.x += fmaxf(h.x, 0.f);
            acc.y += fmaxf(h.y, 0.f);
            acc.z += fmaxf(h.z, 0.f);
            acc.w += fmaxf(h.w, 0.f);
        }
        r4[(long long)node * 32 + lane] = acc;
    }
}

// ---------------- per-graph reduction ----------------
__global__ void k_out(const void* batch) {
    int i = blockIdx.x * blockDim.x + threadIdx.x;
    if (i < NN * 16) {
        int n = i >> 4, j = i & 15;
        int b = load_idx(batch, n, g_is64);
        atomicAdd(&g_out[b * 16 + j], g_t[i]);
    }
}

__global__ void k_copy(float* out) {
    int i = blockIdx.x * blockDim.x + threadIdx.x;
    if (i < GG * 16) out[i] = g_out[i];
}

// ---------------- launch ----------------
extern "C" void kernel_launch(void* const* d_in, const int* in_sizes, int n_in,
                              void* d_out, int out_size) {
    const float* x     = (const float*)d_in[0];
    const float* pos   = (const float*)d_in[1];
    const void*  ei    = d_in[2];
    const void*  batch = d_in[3];
    const float* nW1 = (const float*)d_in[4];
    const float* nb1 = (const float*)d_in[5];
    const float* nW2 = (const float*)d_in[6];
    const float* nb2 = (const float*)d_in[7];
    const float* lW1 = (const float*)d_in[8];
    const float* lb1 = (const float*)d_in[9];
    const float* lW2 = (const float*)d_in[10];
    const float* lb2 = (const float*)d_in[11];
    const float* gW1 = (const float*)d_in[12];
    const float* gb1 = (const float*)d_in[13];
    const float* gW2 = (const float*)d_in[14];
    const float* gb2 = (const float*)d_in[15];
    const float* l1W = (const float*)d_in[16];
    const float* l1b = (const float*)d_in[17];
    const float* l2W = (const float*)d_in[18];
    const float* l2b = (const float*)d_in[19];
    float* out = (float*)d_out;

    const int GB = 296;

    k_detect<<<1, 1024>>>(ei);
    k_init<<<(NN + 255) / 256, 256>>>();
    k_hist<<<(EE + 255) / 256, 256>>>(ei);
    k_scan1<<<NB_SCAN, 1024>>>();
    k_scan2<<<1, 128>>>();
    k_fin<<<NB_SCAN, 1024>>>();
    k_scatter<<<(EE + 255) / 256, 256>>>(ei, pos);

    // q = relu(x@nW1 + nb1)                          -> buf3
    k_gemm<16, 128, 1, true><<<GB, 256>>>(-1, x, nW1, nb1, 3, NN);
    // g_F = nW2@W1h_0, g_c = nb2@W1h_0 ; t0 = q@g_F + g_c -> buf1
    k_combine<<<129, 128>>>(nW2, lW1 + 0 * 132 * 128, nb2);
    k_gemm128<1, false><<<GB, 256>>>(3, nullptr, nullptr, 1, nullptr, 1, NN);

    for (int l = 0; l < LL; l++) {
        const float* W1p = lW1 + l * 132 * 128 + 128 * 128;  // ppf rows of local W1
        // r[i] = sum_edges relu(t[src] + ppf@W1p + b1)   (buf1 -> buf2)
        k_gather<<<1184, 256>>>(W1p, lb1 + l * 128);
        // g_F = lW2_l@gW1_l, g_c = lb2_l@gW1_l
        k_combine<<<129, 128>>>(lW2 + l * 128 * 128, gW1 + l * 128 * 128, lb2 + l * 128);
        // u = relu(r@g_F + gb1 + deg*g_c)                -> buf3
        k_gemm128<3, true><<<GB, 256>>>(2, nullptr, nullptr, 1, gb1 + l * 128, 3, NN);
        // h = relu(u@gW2 + gb2)                          -> buf0
        k_gemm128<1, true><<<GB, 256>>>(3, nullptr, gW2 + l * 128 * 128, 0, gb2 + l * 128, 0, NN);
        if (l + 1 < LL) {
            // t_{l+1} = h @ W1h_{l+1}                    -> buf1
            k_gemm128<0, false><<<GB, 256>>>(0, nullptr, lW1 + (l + 1) * 132 * 128, 0, nullptr, 1, NN);
        }
    }

    // head: buf0 -> buf3 -> buf1 -> out
    k_gemm<128, 64, 1, true><<<GB, 256>>>(0, nullptr, l1W, l1b, 3, NN);
    k_gemm<64, 16, 1, false><<<GB, 256>>>(3, nullptr, l2W, l2b, 1, NN);
    k_out<<<(NN * 16 + 255) / 256, 256>>>(batch);
    k_copy<<<(GG * 16 + 255) / 256, 256>>>(out);
}

// round 8
// speedup vs baseline: 1.5912x; 1.2328x over previous
#include <cuda_runtime.h>
#include <cuda_bf16.h>
#include <math.h>
#include <stdint.h>

#define NN 100000
#define EE 1600000
#define HH 128
#define GG 256
#define LL 3
#define NB_SCAN ((NN + 1023) / 1024)   // 98
#define NTILES ((NN + 127) / 128)      // 782

// padded k-major bf16 tile: 128 rows x 136 halves (272 B row pitch)
#define RPITCH 272
#define TILE_U4 2176   // 128 * 17 uint4

// ---------------- scratch (device globals; no allocation) ----------------
__device__ __align__(16) float g_h[NN * HH];
__device__ __align__(16) float g_t[NN * HH];
__device__ __align__(16) float g_r[NN * HH];
__device__ __align__(16) float g_tmp[NN * HH];
__device__ __align__(16) float g_out[GG * 16];
__device__ __align__(16) float g_F[HH * HH];     // fused weight product
__device__ __align__(16) float g_c[HH];          // fused bias vector
__device__ __align__(16) uint4 g_Bhi[TILE_U4];   // W^T bf16 hi, padded k-major
__device__ __align__(16) uint4 g_Blo[TILE_U4];   // W^T bf16 lo
__device__ int    g_deg[NN];
__device__ int    g_incl[NN];
__device__ int    g_rowptr[NN + 1];
__device__ int    g_cursor[NN];
__device__ int    g_srcs[EE];
__device__ float4 g_ppf[EE];
__device__ int    g_bsum[128];
__device__ int    g_is64;

__device__ __forceinline__ float* getbuf(int id) {
    switch (id) {
        case 0: return g_h;
        case 1: return g_t;
        case 2: return g_r;
        default: return g_tmp;
    }
}

__device__ __forceinline__ int load_idx(const void* p, long long i, int is64) {
    if (is64) return (int)((const long long*)p)[i];
    return ((const int*)p)[i];
}

// ================= mma.sync helpers (baseline sm_80+ PTX) =================
__device__ __forceinline__ uint32_t smem_u32(const void* p) {
    uint32_t a;
    asm("{ .reg .u64 t; cvta.to.shared.u64 t, %1; cvt.u32.u64 %0, t; }" : "=r"(a) : "l"(p));
    return a;
}
__device__ __forceinline__ void ldm4(uint32_t* r, uint32_t addr) {
    asm volatile("ldmatrix.sync.aligned.m8n8.x4.shared.b16 {%0,%1,%2,%3}, [%4];"
        : "=r"(r[0]), "=r"(r[1]), "=r"(r[2]), "=r"(r[3]) : "r"(addr));
}
__device__ __forceinline__ void mma16816(float* d, const uint32_t* a, uint32_t b0, uint32_t b1) {
    asm volatile("mma.sync.aligned.m16n8k16.row.col.f32.bf16.bf16.f32 "
        "{%0,%1,%2,%3}, {%4,%5,%6,%7}, {%8,%9}, {%0,%1,%2,%3};"
        : "+f"(d[0]), "+f"(d[1]), "+f"(d[2]), "+f"(d[3])
        : "r"(a[0]), "r"(a[1]), "r"(a[2]), "r"(a[3]), "r"(b0), "r"(b1));
}

// split 8 floats into bf16 hi / lo packed words
__device__ __forceinline__ void split8(const float* v, uint4& hi, uint4& lo) {
    unsigned hs[8], ls[8];
#pragma unroll
    for (int j = 0; j < 8; j++) {
        __nv_bfloat16 h = __float2bfloat16(v[j]);
        float rem = v[j] - __bfloat162float(h);
        __nv_bfloat16 l = __float2bfloat16(rem);
        hs[j] = (unsigned)__bfloat16_as_ushort(h);
        ls[j] = (unsigned)__bfloat16_as_ushort(l);
    }
    hi = make_uint4(hs[0] | (hs[1] << 16), hs[2] | (hs[3] << 16), hs[4] | (hs[5] << 16), hs[6] | (hs[7] << 16));
    lo = make_uint4(ls[0] | (ls[1] << 16), ls[2] | (ls[3] << 16), ls[4] | (ls[5] << 16), ls[6] | (ls[7] << 16));
}

// ---------------- dtype detection ----------------
__global__ void k_detect(const void* ei) {
    __shared__ int s_nz;
    if (threadIdx.x == 0) s_nz = 0;
    __syncthreads();
    const int* w = (const int*)ei;
    int v = w[2 * threadIdx.x + 1];
    int v2 = w[2 * (threadIdx.x + 1024) + 1];
    if ((v | v2) != 0) atomicOr(&s_nz, 1);
    __syncthreads();
    if (threadIdx.x == 0) g_is64 = s_nz ? 0 : 1;
}

__global__ void k_init() {
    int i = blockIdx.x * blockDim.x + threadIdx.x;
    if (i < GG * 16) g_out[i] = 0.f;
    if (i < NN) g_deg[i] = 0;
}

__global__ void k_hist(const void* ei) {
    int e = blockIdx.x * blockDim.x + threadIdx.x;
    if (e < EE) {
        int d = load_idx(ei, (long long)EE + e, g_is64);
        atomicAdd(&g_deg[d], 1);
    }
}

__global__ void k_scan1() {
    __shared__ int s[1024];
    int tid = threadIdx.x;
    int i = blockIdx.x * 1024 + tid;
    int v = (i < NN) ? g_deg[i] : 0;
    s[tid] = v;
    __syncthreads();
    for (int off = 1; off < 1024; off <<= 1) {
        int a = (tid >= off) ? s[tid - off] : 0;
        __syncthreads();
        s[tid] += a;
        __syncthreads();
    }
    if (i < NN) g_incl[i] = s[tid];
    if (tid == 1023) g_bsum[blockIdx.x] = s[1023];
}

__global__ void k_scan2() {
    __shared__ int s[128];
    int tid = threadIdx.x;
    s[tid] = (tid < NB_SCAN) ? g_bsum[tid] : 0;
    __syncthreads();
    for (int off = 1; off < 128; off <<= 1) {
        int a = (tid >= off) ? s[tid - off] : 0;
        __syncthreads();
        s[tid] += a;
        __syncthreads();
    }
    if (tid < NB_SCAN) g_bsum[tid] = s[tid];
}

__global__ void k_fin() {
    int tid = threadIdx.x;
    int i = blockIdx.x * 1024 + tid;
    if (i < NN) {
        int off = blockIdx.x ? g_bsum[blockIdx.x - 1] : 0;
        int excl = g_incl[i] - g_deg[i] + off;
        g_rowptr[i] = excl;
        g_cursor[i] = excl;
    }
    if (i == 0) g_rowptr[NN] = EE;
}

__device__ __forceinline__ float dot3(float ax, float ay, float az, float bx, float by, float bz) {
    return ax * bx + ay * by + az * bz;
}
__device__ __forceinline__ float crossnorm(float ax, float ay, float az, float bx, float by, float bz) {
    float cx = ay * bz - az * by;
    float cy = az * bx - ax * bz;
    float cz = ax * by - ay * bx;
    return sqrtf(cx * cx + cy * cy + cz * cz);
}

__global__ void k_scatter(const void* ei, const float* pos) {
    int e = blockIdx.x * blockDim.x + threadIdx.x;
    if (e >= EE) return;
    int is64 = g_is64;
    int s = load_idx(ei, e, is64);
    int d = load_idx(ei, (long long)EE + e, is64);
    float pix = pos[3 * d], piy = pos[3 * d + 1], piz = pos[3 * d + 2];
    float pjx = pos[3 * s], pjy = pos[3 * s + 1], pjz = pos[3 * s + 2];
    float nin = sqrtf(pix * pix + piy * piy + piz * piz) + 1e-12f;
    float njn = sqrtf(pjx * pjx + pjy * pjy + pjz * pjz) + 1e-12f;
    float nix = pix / nin, niy = piy / nin, niz = piz / nin;
    float njx = pjx / njn, njy = pjy / njn, njz = pjz / njn;
    float dx = pjx - pix, dy = pjy - piy, dz = pjz - piz;
    float f0 = sqrtf(dx * dx + dy * dy + dz * dz);
    float f1 = atan2f(crossnorm(nix, niy, niz, dx, dy, dz), dot3(nix, niy, niz, dx, dy, dz));
    float f2 = atan2f(crossnorm(njx, njy, njz, dx, dy, dz), dot3(njx, njy, njz, dx, dy, dz));
    float f3 = atan2f(crossnorm(nix, niy, niz, njx, njy, njz), dot3(nix, niy, niz, njx, njy, njz));
    int slot = atomicAdd(&g_cursor[d], 1);
    g_srcs[slot] = s;
    g_ppf[slot] = make_float4(f0, f1, f2, f3);
}

// ---------------- g_F = A@B (128x128), g_c = v@B ----------------
__global__ void k_combine(const float* A, const float* B, const float* v) {
    int col = threadIdx.x;
    int row = blockIdx.x;
    if (row < 128) {
        float s = 0.f;
        for (int k = 0; k < 128; k++) s = fmaf(A[row * 128 + k], B[k * 128 + col], s);
        g_F[row * 128 + col] = s;
    } else {
        float s = 0.f;
        for (int k = 0; k < 128; k++) s = fmaf(v[k], B[k * 128 + col], s);
        g_c[col] = s;
    }
}

// ---------------- weight split: W[k][n] (or g_F) -> g_Bhi/g_Blo as Wt[n][k] bf16, padded ----------------
__global__ void k_split(const float* W, int wsel) {
    const float* src = wsel ? g_F : W;
    int i = blockIdx.x * blockDim.x + threadIdx.x;   // 0..2047
    if (i >= 2048) return;
    int n = i >> 4, kg = i & 15;
    float v[8];
#pragma unroll
    for (int j = 0; j < 8; j++) v[j] = src[(kg * 8 + j) * 128 + n];
    uint4 hi, lo;
    split8(v, hi, lo);
    g_Bhi[n * 17 + kg] = hi;
    g_Blo[n * 17 + kg] = lo;
}

// ---------------- HMMA GEMM: Y = act(X @ W [+ bias|g_c] [+ deg*g_c]), nrows x 128 ----------------
// BMODE: 0 none, 1 bias (bias==nullptr -> g_c), 3 bias + deg*g_c
#define SM_BHI 0
#define SM_BLO 34816
#define SM_AHI 69632
#define SM_ALO 104448
#define SM_BYTES 139264

template <int BMODE, bool RELU>
__global__ void __launch_bounds__(256, 1) k_mmagemm(int xid, const float* bias, int yid, int nrows) {
    extern __shared__ char sm[];
    const float* X = getbuf(xid);
    float* Y = getbuf(yid);

    int tid = threadIdx.x;
    int wid = tid >> 5;
    int lane = tid & 31;

    // persistent weights into smem
    uint4* bhi_s = (uint4*)(sm + SM_BHI);
    uint4* blo_s = (uint4*)(sm + SM_BLO);
    for (int i = tid; i < TILE_U4; i += 256) {
        bhi_s[i] = g_Bhi[i];
        blo_s[i] = g_Blo[i];
    }

    const int mrow0 = (wid & 3) * 32;    // warp's 32 rows
    const int ncol0 = (wid >> 2) * 64;   // warp's 64 cols

    // per-lane ldmatrix address components
    const int lrow = lane & 15;                 // row/col index within 16
    const int lkof = ((lane >> 4) << 3) * 2;    // +8 halves for upper half-warp (bytes)

    uint32_t a_base_hi = smem_u32(sm + SM_AHI);
    uint32_t a_base_lo = smem_u32(sm + SM_ALO);
    uint32_t b_base_hi = smem_u32(sm + SM_BHI);
    uint32_t b_base_lo = smem_u32(sm + SM_BLO);

    for (int tile = blockIdx.x; tile < NTILES; tile += gridDim.x) {
        int row0 = tile * 128;
        __syncthreads();   // smem A free (prev tile consumers done); also covers B on first iter
        // split A tile into smem bf16 hi/lo (k-major, padded rows)
        for (int i = tid; i < 2048; i += 256) {
            int row = i >> 4, grp = i & 15;
            int r = row0 + row;
            float v[8];
            if (r < nrows) {
                float4 v0 = *(const float4*)&X[(long long)r * 128 + grp * 8];
                float4 v1 = *(const float4*)&X[(long long)r * 128 + grp * 8 + 4];
                v[0] = v0.x; v[1] = v0.y; v[2] = v0.z; v[3] = v0.w;
                v[4] = v1.x; v[5] = v1.y; v[6] = v1.z; v[7] = v1.w;
            } else {
#pragma unroll
                for (int j = 0; j < 8; j++) v[j] = 0.f;
            }
            uint4 hi, lo;
            split8(v, hi, lo);
            *(uint4*)(sm + SM_AHI + row * RPITCH + grp * 16) = hi;
            *(uint4*)(sm + SM_ALO + row * RPITCH + grp * 16) = lo;
        }
        __syncthreads();

        float d[2][8][4];
#pragma unroll
        for (int mt = 0; mt < 2; mt++)
#pragma unroll
            for (int nt = 0; nt < 8; nt++)
#pragma unroll
                for (int j = 0; j < 4; j++) d[mt][nt][j] = 0.f;

#pragma unroll
        for (int kk = 0; kk < 8; kk++) {
            int kb = kk * 32 + lkof;   // byte offset of k-chunk for this lane
            uint32_t ah[2][4], al[2][4];
#pragma unroll
            for (int mt = 0; mt < 2; mt++) {
                uint32_t off = (mrow0 + mt * 16 + lrow) * RPITCH + kb;
                ldm4(ah[mt], a_base_hi + off);
                ldm4(al[mt], a_base_lo + off);
            }
            uint32_t bh[4][4], bl[4][4];
#pragma unroll
            for (int np = 0; np < 4; np++) {
                uint32_t off = (ncol0 + np * 16 + lrow) * RPITCH + kb;
                ldm4(bh[np], b_base_hi + off);
                ldm4(bl[np], b_base_lo + off);
            }
#pragma unroll
            for (int mt = 0; mt < 2; mt++) {
#pragma unroll
                for (int np = 0; np < 4; np++) {
                    // even n8 tile: b regs {r0, r2}; odd: {r1, r3}
                    mma16816(d[mt][np * 2],     ah[mt], bh[np][0], bh[np][2]);
                    mma16816(d[mt][np * 2],     ah[mt], bl[np][0], bl[np][2]);
                    mma16816(d[mt][np * 2],     al[mt], bh[np][0], bh[np][2]);
                    mma16816(d[mt][np * 2 + 1], ah[mt], bh[np][1], bh[np][3]);
                    mma16816(d[mt][np * 2 + 1], ah[mt], bl[np][1], bl[np][3]);
                    mma16816(d[mt][np * 2 + 1], al[mt], bh[np][1], bh[np][3]);
                }
            }
        }

        // epilogue: c-frag lane l: {d0,d1} at (row l/4, col 2*(l%4)); {d2,d3} at row+8
        int rbase = row0 + mrow0 + (lane >> 2);
        int cbase = ncol0 + 2 * (lane & 3);
#pragma unroll
        for (int mt = 0; mt < 2; mt++) {
            int r0 = rbase + mt * 16;
            int r1 = r0 + 8;
            float sc0 = 0.f, sc1 = 0.f;
            if (BMODE == 3) {
                if (r0 < nrows) sc0 = (float)g_deg[r0];
                if (r1 < nrows) sc1 = (float)g_deg[r1];
            }
#pragma unroll
            for (int nt = 0; nt < 8; nt++) {
                int c = cbase + nt * 8;
                float b0 = 0.f, b1 = 0.f, c0 = 0.f, c1 = 0.f;
                if (BMODE >= 1) {
                    const float* bp = (bias != nullptr) ? bias : g_c;
                    b0 = bp[c]; b1 = bp[c + 1];
                }
                if (BMODE == 3) { c0 = g_c[c]; c1 = g_c[c + 1]; }
                if (r0 < nrows) {
                    float v0 = d[mt][nt][0] + b0 + sc0 * c0;
                    float v1 = d[mt][nt][1] + b1 + sc0 * c1;
                    if (RELU) { v0 = fmaxf(v0, 0.f); v1 = fmaxf(v1, 0.f); }
                    *(float2*)&Y[(long long)r0 * 128 + c] = make_float2(v0, v1);
                }
                if (r1 < nrows) {
                    float v2 = d[mt][nt][2] + b0 + sc1 * c0;
                    float v3 = d[mt][nt][3] + b1 + sc1 * c1;
                    if (RELU) { v2 = fmaxf(v2, 0.f); v3 = fmaxf(v3, 0.f); }
                    *(float2*)&Y[(long long)r1 * 128 + c] = make_float2(v2, v3);
                }
            }
        }
    }
}

// ---------------- small GEMM (K=16 node in + heads) ----------------
template <int K, int M, int BMODE, bool RELU>
__global__ void k_gemm(int xid, const float* Xext,
                       const float* W, const float* bias,
                       int yid, int nrows) {
    constexpr int NT = 64;
    constexpr int CG = M / 4;
    constexpr int NG = 256 / CG;
    constexpr int NPT = NT / NG;
    constexpr int KC = 16;
    __shared__ float Ws[KC * M];
    __shared__ float Xs[NT * K];

    const float* X = (xid >= 0) ? getbuf(xid) : Xext;
    float* Y = getbuf(yid);

    int tid = threadIdx.x;
    const int c = tid % CG;
    const int g = tid / CG;
    const float4* Ws4 = (const float4*)Ws;
    int ntiles = (nrows + NT - 1) / NT;

    for (int tile = blockIdx.x; tile < ntiles; tile += gridDim.x) {
        int row0 = tile * NT;
        __syncthreads();
        for (int i = tid; i < NT * K; i += 256) {
            int rr = i / K, kk = i % K;
            int r = row0 + rr;
            Xs[i] = (r < nrows) ? X[(long long)r * K + kk] : 0.f;
        }
        float4 acc[NPT];
#pragma unroll
        for (int r = 0; r < NPT; r++) acc[r] = make_float4(0.f, 0.f, 0.f, 0.f);

        for (int kc0 = 0; kc0 < K; kc0 += KC) {
            __syncthreads();
            for (int i = tid; i < KC * M; i += 256) Ws[i] = W[kc0 * M + i];
            __syncthreads();
#pragma unroll
            for (int k = 0; k < KC; k++) {
                float4 w = Ws4[k * CG + c];
#pragma unroll
                for (int r = 0; r < NPT; r++) {
                    float xv = Xs[(g * NPT + r) * K + kc0 + k];
                    acc[r].x = fmaf(xv, w.x, acc[r].x);
                    acc[r].y = fmaf(xv, w.y, acc[r].y);
                    acc[r].z = fmaf(xv, w.z, acc[r].z);
                    acc[r].w = fmaf(xv, w.w, acc[r].w);
                }
            }
        }
        float4 bv = make_float4(0.f, 0.f, 0.f, 0.f);
        if (BMODE >= 1) bv = ((const float4*)bias)[c];
#pragma unroll
        for (int r = 0; r < NPT; r++) {
            int row = row0 + g * NPT + r;
            if (row < nrows) {
                float4 v;
                v.x = acc[r].x + bv.x;
                v.y = acc[r].y + bv.y;
                v.z = acc[r].z + bv.z;
                v.w = acc[r].w + bv.w;
                if (RELU) {
                    v.x = fmaxf(v.x, 0.f);
                    v.y = fmaxf(v.y, 0.f);
                    v.z = fmaxf(v.z, 0.f);
                    v.w = fmaxf(v.w, 0.f);
                }
                ((float4*)Y)[(long long)row * CG + c] = v;
            }
        }
    }
}

// ---------------- edge gather ----------------
__global__ void k_gather(const float* W1p, const float* b1) {
    int lane = threadIdx.x & 31;
    int wid = (blockIdx.x * blockDim.x + threadIdx.x) >> 5;
    int nwarps = (gridDim.x * blockDim.x) >> 5;
    const float4* W4 = (const float4*)W1p;
    float4 w0 = W4[0 * 32 + lane];
    float4 w1 = W4[1 * 32 + lane];
    float4 w2 = W4[2 * 32 + lane];
    float4 w3 = W4[3 * 32 + lane];
    float4 bb = ((const float4*)b1)[lane];
    const float4* t4 = (const float4*)g_t;
    float4* r4 = (float4*)g_r;
    for (int node = wid; node < NN; node += nwarps) {
        int s0 = g_rowptr[node];
        int s1 = g_rowptr[node + 1];
        float4 acc = make_float4(0.f, 0.f, 0.f, 0.f);
        for (int s = s0; s < s1; s++) {
            int src = g_srcs[s];
            float4 pf = g_ppf[s];
            float4 tv = t4[(long long)src * 32 + lane];
            float4 h;
            h.x = bb.x + tv.x;
            h.y = bb.y + tv.y;
            h.z = bb.z + tv.z;
            h.w = bb.w + tv.w;
            h.x = fmaf(pf.x, w0.x, h.x); h.y = fmaf(pf.x, w0.y, h.y); h.z = fmaf(pf.x, w0.z, h.z); h.w = fmaf(pf.x, w0.w, h.w);
            h.x = fmaf(pf.y, w1.x, h.x); h.y = fmaf(pf.y, w1.y, h.y); h.z = fmaf(pf.y, w1.z, h.z); h.w = fmaf(pf.y, w1.w, h.w);
            h.x = fmaf(pf.z, w2.x, h.x); h.y = fmaf(pf.z, w2.y, h.y); h.z = fmaf(pf.z, w2.z, h.z); h.w = fmaf(pf.z, w2.w, h.w);
            h.x = fmaf(pf.w, w3.x, h.x); h.y = fmaf(pf.w, w3.y, h.y); h.z = fmaf(pf.w, w3.z, h.z); h.w = fmaf(pf.w, w3.w, h.w);
            acc.x += fmaxf(h.x, 0.f);
            acc.y += fmaxf(h.y, 0.f);
            acc.z += fmaxf(h.z, 0.f);
            acc.w += fmaxf(h.w, 0.f);
        }
        r4[(long long)node * 32 + lane] = acc;
    }
}

// ---------------- per-graph reduction ----------------
__global__ void k_out(const void* batch) {
    int i = blockIdx.x * blockDim.x + threadIdx.x;
    if (i < NN * 16) {
        int n = i >> 4, j = i & 15;
        int b = load_idx(batch, n, g_is64);
        atomicAdd(&g_out[b * 16 + j], g_t[i]);
    }
}

__global__ void k_copy(float* out) {
    int i = blockIdx.x * blockDim.x + threadIdx.x;
    if (i < GG * 16) out[i] = g_out[i];
}

// ---------------- launch ----------------
extern "C" void kernel_launch(void* const* d_in, const int* in_sizes, int n_in,
                              void* d_out, int out_size) {
    const float* x     = (const float*)d_in[0];
    const float* pos   = (const float*)d_in[1];
    const void*  ei    = d_in[2];
    const void*  batch = d_in[3];
    const float* nW1 = (const float*)d_in[4];
    const float* nb1 = (const float*)d_in[5];
    const float* nW2 = (const float*)d_in[6];
    const float* nb2 = (const float*)d_in[7];
    const float* lW1 = (const float*)d_in[8];
    const float* lb1 = (const float*)d_in[9];
    const float* lW2 = (const float*)d_in[10];
    const float* lb2 = (const float*)d_in[11];
    const float* gW1 = (const float*)d_in[12];
    const float* gb1 = (const float*)d_in[13];
    const float* gW2 = (const float*)d_in[14];
    const float* gb2 = (const float*)d_in[15];
    const float* l1W = (const float*)d_in[16];
    const float* l1b = (const float*)d_in[17];
    const float* l2W = (const float*)d_in[18];
    const float* l2b = (const float*)d_in[19];
    float* out = (float*)d_out;

    cudaFuncSetAttribute(k_mmagemm<0, false>, cudaFuncAttributeMaxDynamicSharedMemorySize, SM_BYTES);
    cudaFuncSetAttribute(k_mmagemm<1, false>, cudaFuncAttributeMaxDynamicSharedMemorySize, SM_BYTES);
    cudaFuncSetAttribute(k_mmagemm<1, true>,  cudaFuncAttributeMaxDynamicSharedMemorySize, SM_BYTES);
    cudaFuncSetAttribute(k_mmagemm<3, true>,  cudaFuncAttributeMaxDynamicSharedMemorySize, SM_BYTES);

    const int GB = 296;
    const int GT = 148;

    k_detect<<<1, 1024>>>(ei);
    k_init<<<(NN + 255) / 256, 256>>>();
    k_hist<<<(EE + 255) / 256, 256>>>(ei);
    k_scan1<<<NB_SCAN, 1024>>>();
    k_scan2<<<1, 128>>>();
    k_fin<<<NB_SCAN, 1024>>>();
    k_scatter<<<(EE + 255) / 256, 256>>>(ei, pos);

    // q = relu(x@nW1 + nb1)                          -> buf3
    k_gemm<16, 128, 1, true><<<GB, 256>>>(-1, x, nW1, nb1, 3, NN);
    // g_F = nW2@W1h_0, g_c = nb2@W1h_0 ; t0 = q@g_F + g_c -> buf1
    k_combine<<<129, 128>>>(nW2, lW1 + 0 * 132 * 128, nb2);
    k_split<<<8, 256>>>(nullptr, 1);
    k_mmagemm<1, false><<<GT, 256, SM_BYTES>>>(3, nullptr, 1, NN);

    for (int l = 0; l < LL; l++) {
        const float* W1p = lW1 + l * 132 * 128 + 128 * 128;  // ppf rows of local W1
        // r[i] = sum_edges relu(t[src] + ppf@W1p + b1)   (buf1 -> buf2)
        k_gather<<<1184, 256>>>(W1p, lb1 + l * 128);
        // g_F = lW2_l@gW1_l, g_c = lb2_l@gW1_l
        k_combine<<<129, 128>>>(lW2 + l * 128 * 128, gW1 + l * 128 * 128, lb2 + l * 128);
        k_split<<<8, 256>>>(nullptr, 1);
        // u = relu(r@g_F + gb1 + deg*g_c)                -> buf3
        k_mmagemm<3, true><<<GT, 256, SM_BYTES>>>(2, gb1 + l * 128, 3, NN);
        // h = relu(u@gW2 + gb2)                          -> buf0
        k_split<<<8, 256>>>(gW2 + l * 128 * 128, 0);
        k_mmagemm<1, true><<<GT, 256, SM_BYTES>>>(3, gb2 + l * 128, 0, NN);
        if (l + 1 < LL) {
            // t_{l+1} = h @ W1h_{l+1}                    -> buf1
            k_split<<<8, 256>>>(lW1 + (l + 1) * 132 * 128, 0);
            k_mmagemm<0, false><<<GT, 256, SM_BYTES>>>(0, nullptr, 1, NN);
        }
    }

    // head: buf0 -> buf3 -> buf1 -> out
    k_gemm<128, 64, 1, true><<<GB, 256>>>(0, nullptr, l1W, l1b, 3, NN);
    k_gemm<64, 16, 1, false><<<GB, 256>>>(3, nullptr, l2W, l2b, 1, NN);
    k_out<<<(NN * 16 + 255) / 256, 256>>>(batch);
    k_copy<<<(GG * 16 + 255) / 256, 256>>>(out);
}